// round 12
// baseline (speedup 1.0000x reference)
#include <cuda_runtime.h>
#include <cuda_bf16.h>
#include <math.h>
#include <stdint.h>

// ---------------- problem constants ----------------
#define BATCH   8
#define NPTS    16384
#define NPOINT  1024
#define NSAMPLE 32
#define NTOT    (BATCH * NPOINT * NSAMPLE)   // 262144 rows through the MLP
#define C0      6
#define C1      64
#define C2      64
#define C3      128

#define FPS_THREADS 1024
#define FPS_PAIRS   (NPTS / (2 * FPS_THREADS))   // 8 pairs -> 16 points per thread
#define FPS_WARPS   (FPS_THREADS / 32)           // 32
#define CELLS       512                          // 8x8x8 morton grid

#define FPS_SMEM    (NPTS / 2 * (sizeof(float2) + sizeof(uint2)))   // 128KB dynamic

typedef unsigned long long u64;

// ---------------- device scratch (no allocations allowed) ----------------
__device__ float  g_sorted[(size_t)BATCH * NPTS * 3];
__device__ int    g_sorig[(size_t)BATCH * NPTS];
__device__ float  g_feat0[(size_t)NTOT * C0];
__device__ float  g_act1[(size_t)NTOT * C1];
__device__ float  g_act2[(size_t)NTOT * C2];
__device__ float  g_act3[(size_t)NTOT * C3];
__device__ double g_sum[3 * 128];
__device__ double g_sq[3 * 128];
__device__ float  g_sA[3 * 128];
__device__ float  g_sB[3 * 128];
__device__ int    g_ctr[3];

// ---------------- packed f32x2 helpers (Blackwell) ----------------
__device__ __forceinline__ void f2_add(u64& o, u64 a, u64 b) {
    asm("add.rn.f32x2 %0, %1, %2;" : "=l"(o) : "l"(a), "l"(b));
}
__device__ __forceinline__ void f2_mul(u64& o, u64 a, u64 b) {
    asm("mul.rn.f32x2 %0, %1, %2;" : "=l"(o) : "l"(a), "l"(b));
}
__device__ __forceinline__ void f2_fma(u64& d, u64 a, u64 b) {
    asm("fma.rn.f32x2 %0, %1, %2, %3;" : "=l"(d) : "l"(a), "l"(b), "l"(d));
}
__device__ __forceinline__ u64 f2_pack(float lo, float hi) {
    u64 r;
    asm("mov.b64 %0, {%1, %2};" : "=l"(r) : "f"(lo), "f"(hi));
    return r;
}
__device__ __forceinline__ void f2_unpack(float& lo, float& hi, u64 v) {
    asm("mov.b64 {%0, %1}, %2;" : "=f"(lo), "=f"(hi) : "l"(v));
}

// ---------------- morton cell id (8x8x8) ----------------
__device__ __forceinline__ int cellco(float v) {
    int c = (int)(v * 8.0f);
    return c < 0 ? 0 : (c > 7 ? 7 : c);
}
__device__ __forceinline__ int morton3(int x, int y, int z) {
    return  (x & 1)        | ((y & 1) << 1) | ((z & 1) << 2)
         | ((x & 2) << 2)  | ((y & 2) << 3) | ((z & 2) << 4)
         | ((x & 4) << 4)  | ((y & 4) << 5) | ((z & 4) << 6);
}

// ---------------- counting sort by morton cell: one block per batch ----------------
__global__ __launch_bounds__(512)
void sort_kernel(const float* __restrict__ xyz,
                 float* __restrict__ xs, int* __restrict__ so)
{
    __shared__ int cnt[CELLS];
    __shared__ int wsum[16];

    const int b    = blockIdx.x;
    const int tid  = threadIdx.x;
    const int lane = tid & 31;
    const int wid  = tid >> 5;
    const float* x = xyz + (size_t)b * NPTS * 3;
    float* xout    = xs + (size_t)b * NPTS * 3;
    int*   sout    = so + (size_t)b * NPTS;

    cnt[tid] = 0;
    __syncthreads();

    int mycell[32];
#pragma unroll
    for (int i = 0; i < 32; i++) {
        int j = tid + i * 512;
        int c = morton3(cellco(x[3 * j + 0]), cellco(x[3 * j + 1]), cellco(x[3 * j + 2]));
        mycell[i] = c;
        atomicAdd(&cnt[c], 1);
    }
    __syncthreads();

    // exclusive prefix sum over 512 counts
    int v = cnt[tid];
    int incl = v;
#pragma unroll
    for (int o = 1; o < 32; o <<= 1) {
        int u = __shfl_up_sync(0xFFFFFFFFu, incl, o);
        if (lane >= o) incl += u;
    }
    if (lane == 31) wsum[wid] = incl;
    __syncthreads();
    if (wid == 0 && lane < 16) {
        int w = wsum[lane];
        int wi = w;
#pragma unroll
        for (int o = 1; o < 16; o <<= 1) {
            int u = __shfl_up_sync(0x0000FFFFu, wi, o);
            if (lane >= o) wi += u;
        }
        wsum[lane] = wi - w;                       // exclusive warp base
    }
    __syncthreads();
    int excl = incl - v + wsum[wid];
    __syncthreads();
    cnt[tid] = excl;                               // running offsets
    __syncthreads();

#pragma unroll
    for (int i = 0; i < 32; i++) {
        int j = tid + i * 512;
        int pos = atomicAdd(&cnt[mycell[i]], 1);
        xout[3 * pos + 0] = x[3 * j + 0];
        xout[3 * pos + 1] = x[3 * j + 1];
        xout[3 * pos + 2] = x[3 * j + 2];
        sout[pos] = j;
    }
}

// ---------------- FPS: 1024 threads/block, spatially pruned ----------------
// Thread t owns sorted points [16t, 16t+16); pair i lives at smem slot t+1024i
// (conflict-free). Tiebreak keys (orig<<14|pos) in a slot-aligned smem uint2
// table; per-thread bbox in STATIC smem (saves 6 regs at the 64-reg budget).
// Invariant: every d_j <= gmax. Warp skips the update iff every lane's bbox is
// provably outside radius sqrt(gmax) of c.
__global__ __launch_bounds__(FPS_THREADS, 1)
void fps_kernel(const float* __restrict__ xyz,       // orig (for first centroid)
                const float* __restrict__ xs,        // sorted coords
                const int*   __restrict__ so,        // sorted -> orig index
                float* __restrict__ newxyz)
{
    extern __shared__ char smemraw[];
    float2* sdist2 = reinterpret_cast<float2*>(smemraw);            // 8192 x 8B
    uint2*  skey2  = reinterpret_cast<uint2*>(smemraw + NPTS / 2 * sizeof(float2));
    __shared__ __align__(16) float4 sbbA[FPS_THREADS];   // (bx0,bx1,by0,by1) 16KB
    __shared__ __align__(16) float2 sbbB[FPS_THREADS];   // (bz0,bz1)          8KB
    __shared__ unsigned sval[FPS_WARPS];
    __shared__ unsigned sidx[FPS_WARPS];

    const int b    = blockIdx.x;
    const int tid  = threadIdx.x;
    const int lane = tid & 31;
    const int wid  = tid >> 5;
    const float* x  = xs + (size_t)b * NPTS * 3;
    const int*   sg = so + (size_t)b * NPTS;

    u64 px[FPS_PAIRS], py[FPS_PAIRS], pz[FPS_PAIRS];
    {
        float bx0 = 1e30f, bx1 = -1e30f, by0 = 1e30f, by1 = -1e30f;
        float bz0 = 1e30f, bz1 = -1e30f;
#pragma unroll
        for (int i = 0; i < FPS_PAIRS; i++) {
            const float2* c6 = reinterpret_cast<const float2*>(x + 6 * (FPS_PAIRS * tid + i));
            float2 a = c6[0], bb = c6[1], cc = c6[2];    // x0 y0 | z0 x1 | y1 z1
            px[i] = f2_pack(a.x, bb.y);
            py[i] = f2_pack(a.y, cc.x);
            pz[i] = f2_pack(bb.x, cc.y);
            bx0 = fminf(bx0, fminf(a.x, bb.y)); bx1 = fmaxf(bx1, fmaxf(a.x, bb.y));
            by0 = fminf(by0, fminf(a.y, cc.x)); by1 = fmaxf(by1, fmaxf(a.y, cc.x));
            bz0 = fminf(bz0, fminf(bb.x, cc.y)); bz1 = fmaxf(bz1, fmaxf(bb.x, cc.y));
            int slot = tid + FPS_THREADS * i;
            sdist2[slot] = make_float2(1e10f, 1e10f);
            int pos0 = 2 * (FPS_PAIRS * tid + i);
            skey2[slot] = make_uint2(((unsigned)sg[pos0] << 14) | (unsigned)pos0,
                                     ((unsigned)sg[pos0 + 1] << 14) | (unsigned)(pos0 + 1));
        }
        sbbA[tid] = make_float4(bx0, bx1, by0, by1);
        sbbB[tid] = make_float2(bz0, bz1);
    }
    __syncthreads();

    // first farthest = ORIGINAL index 0
    const float* x0p = xyz + (size_t)b * NPTS * 3;
    float cx = x0p[0], cy = x0p[1], cz = x0p[2];
    float gmaxf = 1e30f;
    float vmax  = -1.0f;                             // cached max of this thread's 16 d

    for (int s = 0; s < NPOINT; s++) {
        if (tid == 0) {
            float* o = newxyz + (size_t)(b * NPOINT + s) * 3;
            o[0] = cx; o[1] = cy; o[2] = cz;
        }
        // min squared distance from c to this thread's bbox (conservative margin)
        bool touched;
        {
            float4 ba = sbbA[tid];
            float2 bbz = sbbB[tid];
            float ex = fmaxf(fmaxf(ba.x - cx, cx - ba.y), 0.0f);
            float ey = fmaxf(fmaxf(ba.z - cy, cy - ba.w), 0.0f);
            float ez = fmaxf(fmaxf(bbz.x - cz, cz - bbz.y), 0.0f);
            float bd2 = ex * ex + ey * ey + ez * ez;
            touched = !(bd2 > gmaxf * 1.00002f);
        }

        if (__any_sync(0xFFFFFFFFu, touched)) {      // warp-uniform gate
            const u64 ncx = f2_pack(-cx, -cx);
            const u64 ncy = f2_pack(-cy, -cy);
            const u64 ncz = f2_pack(-cz, -cz);
            float v0 = -1.0f, v1 = -1.0f;
#pragma unroll
            for (int i = 0; i < FPS_PAIRS; i++) {
                int slot = tid + FPS_THREADS * i;
                u64 dx, dy, dz, acc;
                f2_add(dx, px[i], ncx);
                f2_add(dy, py[i], ncy);
                f2_add(dz, pz[i], ncz);
                f2_mul(dx, dx, dx);
                f2_mul(dy, dy, dy);
                f2_mul(dz, dz, dz);
                f2_add(acc, dx, dy);
                f2_add(acc, acc, dz);
                float d0, d1;
                f2_unpack(d0, d1, acc);
                float2 dd = sdist2[slot];
                float n0 = fminf(dd.x, d0);
                float n1 = fminf(dd.y, d1);
                sdist2[slot] = make_float2(n0, n1);
                v0 = fmaxf(v0, n0);
                v1 = fmaxf(v1, n1);
            }
            vmax = fmaxf(v0, v1);
        }

        const unsigned bits = __float_as_uint(vmax); // positive: bit order == value order
        const unsigned wmax = __reduce_max_sync(0xFFFFFFFFu, bits);
        if (lane == 0) sval[wid] = wmax;
        __syncthreads();                             // bar1

        const unsigned gbits = __reduce_max_sync(0xFFFFFFFFu, sval[lane]);

        if (lane == 0) sidx[wid] = 0xFFFFFFFFu;      // default: not a winner
        if (wmax == gbits) {                         // winner warp(s) rescan own entries
            unsigned cand = 0xFFFFFFFFu;
#pragma unroll
            for (int i = 0; i < FPS_PAIRS; i++) {
                int slot = tid + FPS_THREADS * i;
                float2 dd = sdist2[slot];
                uint2  kk = skey2[slot];
                if (__float_as_uint(dd.x) == gbits) cand = min(cand, kk.x);
                if (__float_as_uint(dd.y) == gbits) cand = min(cand, kk.y);
            }
            cand = __reduce_min_sync(0xFFFFFFFFu, cand);
            if (lane == 0) sidx[wid] = cand;
        }
        __syncthreads();                             // bar2

        const unsigned gc = __reduce_min_sync(0xFFFFFFFFu, sidx[lane]);
        const int pos = (int)(gc & 0x3FFFu);
        cx = __ldg(x + 3 * pos + 0);
        cy = __ldg(x + 3 * pos + 1);
        cz = __ldg(x + 3 * pos + 2);
        gmaxf = __uint_as_float(gbits);
    }
}

// ---------------- ball query + gather + feature build: one warp per center ----------------
__global__ __launch_bounds__(256)
void ballq_feat_kernel(const float* __restrict__ xyz,
                       const float* __restrict__ points,
                       const float* __restrict__ newxyz,
                       float* __restrict__ feat0)
{
    const float R2 = (float)(0.2 * 0.2);
    const int warp = threadIdx.x >> 5;
    const int lane = threadIdx.x & 31;
    const int gw   = blockIdx.x * 8 + warp;     // 0..8191 center id
    const int b    = gw >> 10;

    const float* x = xyz + (size_t)b * NPTS * 3;
    const float cx = newxyz[gw * 3 + 0];
    const float cy = newxyz[gw * 3 + 1];
    const float cz = newxyz[gw * 3 + 2];

    __shared__ int slist[8][NSAMPLE];

    int cnt = 0;
    for (int j0 = 0; j0 < NPTS; j0 += 32) {
        int j = j0 + lane;
        float dx = __fadd_rn(x[3 * j + 0], -cx);
        float dy = __fadd_rn(x[3 * j + 1], -cy);
        float dz = __fadd_rn(x[3 * j + 2], -cz);
        float d  = __fadd_rn(__fadd_rn(__fmul_rn(dx, dx), __fmul_rn(dy, dy)),
                             __fmul_rn(dz, dz));
        bool inb = !(d > R2);
        unsigned mask = __ballot_sync(0xFFFFFFFFu, inb);
        int pos = cnt + __popc(mask & ((1u << lane) - 1u));
        if (inb && pos < NSAMPLE) slist[warp][pos] = j;
        cnt += __popc(mask);
        if (cnt >= NSAMPLE) break;
    }
    __syncwarp();

    int m = cnt < NSAMPLE ? cnt : NSAMPLE;
    int idx = (lane < m) ? slist[warp][lane] : slist[warp][0];

    const float* p = points + (size_t)b * NPTS * 3;
    size_t o = (size_t)(gw * NSAMPLE + lane) * C0;
    feat0[o + 0] = x[3 * idx + 0] - cx;
    feat0[o + 1] = x[3 * idx + 1] - cy;
    feat0[o + 2] = x[3 * idx + 2] - cz;
    feat0[o + 3] = p[3 * idx + 0];
    feat0[o + 4] = p[3 * idx + 1];
    feat0[o + 5] = p[3 * idx + 2];
}

// ---------------- first conv(1x1): CIN=6, raw output ----------------
__global__ __launch_bounds__(256)
void layer1_kernel(const float* __restrict__ X, const float* __restrict__ W,
                   const float* __restrict__ Bb, float* __restrict__ Y)
{
    __shared__ __align__(16) float Ws[C1 * C0];
    __shared__ float Bs[C1];

    const int tid = threadIdx.x;
    for (int i = tid; i < C1 * C0; i += 256) Ws[i] = W[i];
    for (int i = tid; i < C1; i += 256) Bs[i] = Bb[i];
    __syncthreads();

    const size_t n = (size_t)blockIdx.x * 256 + tid;

    float xin[C0];
#pragma unroll
    for (int c = 0; c < C0; c++) xin[c] = X[n * C0 + c];

    float4* Y4 = reinterpret_cast<float4*>(Y + n * C1);
#pragma unroll 2
    for (int og = 0; og < C1 / 4; og++) {
        float acc[4];
#pragma unroll
        for (int u = 0; u < 4; u++) {
            acc[u] = Bs[4 * og + u];
#pragma unroll
            for (int c = 0; c < C0; c++) acc[u] += xin[c] * Ws[(4 * og + u) * C0 + c];
        }
        Y4[og] = make_float4(acc[0], acc[1], acc[2], acc[3]);
    }
}

// ---------------- packed-FFMA2 conv: CIN=64, COUT templated ----------------
template<int COUT>
__global__ __launch_bounds__(256)
void layer_packed_kernel(const float* __restrict__ X, const float* __restrict__ W,
                         const float* __restrict__ Bb,
                         const float* __restrict__ sA, const float* __restrict__ sB,
                         float* __restrict__ Y)
{
    constexpr int CIN = 64;
    constexpr int OP  = COUT / 2;                  // output pairs
    __shared__ __align__(16) u64 Ws2[CIN][OP];
    __shared__ __align__(16) u64 Bs2[OP];
    __shared__ float sAs[CIN], sBs[CIN];

    const int tid = threadIdx.x;

    for (int idx = tid; idx < CIN * OP; idx += 256) {
        int c  = idx / OP;
        int op = idx - c * OP;
        Ws2[c][op] = f2_pack(W[(2 * op) * CIN + c], W[(2 * op + 1) * CIN + c]);
    }
    for (int op = tid; op < OP; op += 256) Bs2[op] = f2_pack(Bb[2 * op], Bb[2 * op + 1]);
    for (int i = tid; i < CIN; i += 256) { sAs[i] = sA[i]; sBs[i] = sB[i]; }
    __syncthreads();

    const size_t n = (size_t)blockIdx.x * 256 + tid;

    float xin[CIN];
    {
        const float4* X4 = reinterpret_cast<const float4*>(X + n * CIN);
#pragma unroll
        for (int c4 = 0; c4 < CIN / 4; c4++) {
            float4 v = X4[c4];
            xin[4 * c4 + 0] = v.x; xin[4 * c4 + 1] = v.y;
            xin[4 * c4 + 2] = v.z; xin[4 * c4 + 3] = v.w;
        }
#pragma unroll
        for (int c = 0; c < CIN; c++)
            xin[c] = fmaxf(__fmaf_rn(xin[c], sAs[c], sBs[c]), 0.f);
    }

    float4* Y4 = reinterpret_cast<float4*>(Y + n * COUT);
#pragma unroll 1
    for (int og = 0; og < COUT / 16; og++) {
        u64 acc2[8];
#pragma unroll
        for (int k = 0; k < 8; k++) acc2[k] = Bs2[og * 8 + k];
#pragma unroll
        for (int c = 0; c < CIN; c++) {
            const u64 x2 = f2_pack(xin[c], xin[c]);
            const ulonglong2* wp = reinterpret_cast<const ulonglong2*>(&Ws2[c][og * 8]);
#pragma unroll
            for (int k4 = 0; k4 < 4; k4++) {
                ulonglong2 w = wp[k4];
                f2_fma(acc2[2 * k4 + 0], x2, w.x);
                f2_fma(acc2[2 * k4 + 1], x2, w.y);
            }
        }
#pragma unroll
        for (int q = 0; q < 4; q++) {
            float o0, o1, o2, o3;
            f2_unpack(o0, o1, acc2[2 * q + 0]);
            f2_unpack(o2, o3, acc2[2 * q + 1]);
            Y4[og * 4 + q] = make_float4(o0, o1, o2, o3);
        }
    }
}

// ---------------- per-channel sum/sumsq + fused BN finalize (last block) ----------------
template<int C>
__global__ __launch_bounds__(256)
void stats_kernel(const float* __restrict__ Y,
                  double* __restrict__ gsum, double* __restrict__ gsq,
                  const float* __restrict__ g, const float* __restrict__ be,
                  float* __restrict__ sA, float* __restrict__ sB,
                  int* __restrict__ ctr)
{
    __shared__ float ssum[C];
    __shared__ float ssq[C];
    __shared__ bool  slast;
    const int tid = threadIdx.x;
    for (int i = tid; i < C; i += 256) { ssum[i] = 0.f; ssq[i] = 0.f; }
    __syncthreads();

    const float4* Y4 = reinterpret_cast<const float4*>(Y);
    const size_t total4 = (size_t)NTOT * C / 4;
    const size_t stride = (size_t)gridDim.x * 256;      // 4*stride % C == 0 (C|1024)
    const size_t i0 = (size_t)blockIdx.x * 256 + tid;

    float s0 = 0.f, s1 = 0.f, s2 = 0.f, s3 = 0.f;
    float q0 = 0.f, q1 = 0.f, q2 = 0.f, q3 = 0.f;
    for (size_t i = i0; i < total4; i += stride) {
        float4 v = Y4[i];
        s0 += v.x; s1 += v.y; s2 += v.z; s3 += v.w;
        q0 = __fmaf_rn(v.x, v.x, q0); q1 = __fmaf_rn(v.y, v.y, q1);
        q2 = __fmaf_rn(v.z, v.z, q2); q3 = __fmaf_rn(v.w, v.w, q3);
    }
    const int cb = (int)((4 * i0) % C);
    atomicAdd(&ssum[cb + 0], s0); atomicAdd(&ssq[cb + 0], q0);
    atomicAdd(&ssum[cb + 1], s1); atomicAdd(&ssq[cb + 1], q1);
    atomicAdd(&ssum[cb + 2], s2); atomicAdd(&ssq[cb + 2], q2);
    atomicAdd(&ssum[cb + 3], s3); atomicAdd(&ssq[cb + 3], q3);
    __syncthreads();
    for (int c = tid; c < C; c += 256) {
        atomicAdd(&gsum[c], (double)ssum[c]);
        atomicAdd(&gsq[c],  (double)ssq[c]);
    }
    __threadfence();
    if (tid == 0) slast = (atomicAdd(ctr, 1) == (int)gridDim.x - 1);
    __syncthreads();
    if (slast && tid < C) {
        double mu  = gsum[tid] / (double)NTOT;
        double var = gsq[tid] / (double)NTOT - mu * mu;
        float rsig = rsqrtf((float)var + 1e-5f);
        float a = g[tid] * rsig;
        sA[tid] = a;
        sB[tid] = be[tid] - (float)mu * a;
    }
}

// ---------------- final BN + ReLU + max over K ----------------
__global__ __launch_bounds__(128)
void maxpool_kernel(const float* __restrict__ act3,
                    const float* __restrict__ sA, const float* __restrict__ sB,
                    float* __restrict__ out)
{
    const int bs = blockIdx.x;          // 0..8191
    const int c  = threadIdx.x;         // 0..127
    const float a = sA[c], b = sB[c];
    size_t base = (size_t)bs * NSAMPLE * C3;
    float m = -1e30f;
#pragma unroll 8
    for (int k = 0; k < NSAMPLE; k++) {
        float v = fmaxf(__fmaf_rn(__ldg(act3 + base + (size_t)k * C3 + c), a, b), 0.f);
        m = fmaxf(m, v);
    }
    out[(size_t)bs * C3 + c] = m;
}

__global__ void zero_stats(double* gsum, double* gsq, int* ctr)
{
    int i = threadIdx.x;
    if (i < 384) { gsum[i] = 0.0; gsq[i] = 0.0; }
    if (i < 3) ctr[i] = 0;
}

// ---------------- launch ----------------
extern "C" void kernel_launch(void* const* d_in, const int* in_sizes, int n_in,
                              void* d_out, int out_size)
{
    const float* xyz = (const float*)d_in[0];
    const float* pts = (const float*)d_in[1];
    const float* w0  = (const float*)d_in[2];
    const float* b0  = (const float*)d_in[3];
    const float* g0  = (const float*)d_in[4];
    const float* be0 = (const float*)d_in[5];
    const float* w1  = (const float*)d_in[6];
    const float* b1  = (const float*)d_in[7];
    const float* g1  = (const float*)d_in[8];
    const float* be1 = (const float*)d_in[9];
    const float* w2  = (const float*)d_in[10];
    const float* b2  = (const float*)d_in[11];
    const float* g2  = (const float*)d_in[12];
    const float* be2 = (const float*)d_in[13];

    float* out    = (float*)d_out;
    float* newxyz = out;                              // (8,1024,3)
    float* newpts = out + BATCH * NPOINT * 3;         // (8,1024,128)

    float *feat0, *act1, *act2, *act3, *sA, *sB, *xs;
    int *so, *ctr;
    double *gsum, *gsq;
    cudaGetSymbolAddress((void**)&xs,    g_sorted);
    cudaGetSymbolAddress((void**)&so,    g_sorig);
    cudaGetSymbolAddress((void**)&feat0, g_feat0);
    cudaGetSymbolAddress((void**)&act1,  g_act1);
    cudaGetSymbolAddress((void**)&act2,  g_act2);
    cudaGetSymbolAddress((void**)&act3,  g_act3);
    cudaGetSymbolAddress((void**)&gsum,  g_sum);
    cudaGetSymbolAddress((void**)&gsq,   g_sq);
    cudaGetSymbolAddress((void**)&sA,    g_sA);
    cudaGetSymbolAddress((void**)&sB,    g_sB);
    cudaGetSymbolAddress((void**)&ctr,   g_ctr);

    cudaFuncSetAttribute(fps_kernel,
                         cudaFuncAttributeMaxDynamicSharedMemorySize,
                         FPS_SMEM);

    // 2 pads: profiler captures launch index 3 -> fps_kernel (sort is idx 2)
    for (int r = 0; r < 2; r++) zero_stats<<<1, 384>>>(gsum, gsq, ctr);

    sort_kernel<<<BATCH, 512>>>(xyz, xs, so);
    fps_kernel<<<BATCH, FPS_THREADS, FPS_SMEM>>>(xyz, xs, so, newxyz);
    ballq_feat_kernel<<<(BATCH * NPOINT) / 8, 256>>>(xyz, pts, newxyz, feat0);

    layer1_kernel<<<NTOT / 256, 256>>>(feat0, w0, b0, act1);
    stats_kernel<C1><<<1184, 256>>>(act1, gsum + 0, gsq + 0,
                                    g0, be0, sA + 0, sB + 0, ctr + 0);

    layer_packed_kernel<C2><<<NTOT / 256, 256>>>(act1, w1, b1, sA + 0, sB + 0, act2);
    stats_kernel<C2><<<1184, 256>>>(act2, gsum + 128, gsq + 128,
                                    g1, be1, sA + 128, sB + 128, ctr + 1);

    layer_packed_kernel<C3><<<NTOT / 256, 256>>>(act2, w2, b2, sA + 128, sB + 128, act3);
    stats_kernel<C3><<<1184, 256>>>(act3, gsum + 256, gsq + 256,
                                    g2, be2, sA + 256, sB + 256, ctr + 2);

    maxpool_kernel<<<BATCH * NPOINT, 128>>>(act3, sA + 256, sB + 256, newpts);
}

// round 13
// speedup vs baseline: 1.1108x; 1.1108x over previous
#include <cuda_runtime.h>
#include <cuda_bf16.h>
#include <math.h>
#include <stdint.h>

// ---------------- problem constants ----------------
#define BATCH   8
#define NPTS    16384
#define NPOINT  1024
#define NSAMPLE 32
#define NTOT    (BATCH * NPOINT * NSAMPLE)   // 262144 rows through the MLP
#define C0      6
#define C1      64
#define C2      64
#define C3      128

#define FPS_THREADS 512
#define FPS_PAIRS   (NPTS / (2 * FPS_THREADS))   // 16 pairs -> 32 points per thread
#define FPS_WARPS   (FPS_THREADS / 32)           // 16
#define CELLS       512                          // 8x8x8 morton grid

#define FPS_SMEM    (NPTS / 2 * (sizeof(float2) + sizeof(uint2)))   // 128KB

typedef unsigned long long u64;

// ---------------- device scratch (no allocations allowed) ----------------
__device__ float  g_sorted[(size_t)BATCH * NPTS * 3];
__device__ int    g_sorig[(size_t)BATCH * NPTS];
__device__ float  g_feat0[(size_t)NTOT * C0];
__device__ float  g_act1[(size_t)NTOT * C1];
__device__ float  g_act2[(size_t)NTOT * C2];
__device__ float  g_act3[(size_t)NTOT * C3];
__device__ double g_sum[3 * 128];
__device__ double g_sq[3 * 128];
__device__ float  g_sA[3 * 128];
__device__ float  g_sB[3 * 128];
__device__ int    g_ctr[3];

// ---------------- packed f32x2 helpers (Blackwell) ----------------
__device__ __forceinline__ void f2_add(u64& o, u64 a, u64 b) {
    asm("add.rn.f32x2 %0, %1, %2;" : "=l"(o) : "l"(a), "l"(b));
}
__device__ __forceinline__ void f2_mul(u64& o, u64 a, u64 b) {
    asm("mul.rn.f32x2 %0, %1, %2;" : "=l"(o) : "l"(a), "l"(b));
}
__device__ __forceinline__ void f2_fma(u64& d, u64 a, u64 b) {
    asm("fma.rn.f32x2 %0, %1, %2, %3;" : "=l"(d) : "l"(a), "l"(b), "l"(d));
}
__device__ __forceinline__ u64 f2_pack(float lo, float hi) {
    u64 r;
    asm("mov.b64 %0, {%1, %2};" : "=l"(r) : "f"(lo), "f"(hi));
    return r;
}
__device__ __forceinline__ void f2_unpack(float& lo, float& hi, u64 v) {
    asm("mov.b64 {%0, %1}, %2;" : "=f"(lo), "=f"(hi) : "l"(v));
}

// ---------------- morton cell id (8x8x8) ----------------
__device__ __forceinline__ int cellco(float v) {
    int c = (int)(v * 8.0f);
    return c < 0 ? 0 : (c > 7 ? 7 : c);
}
__device__ __forceinline__ int morton3(int x, int y, int z) {
    return  (x & 1)        | ((y & 1) << 1) | ((z & 1) << 2)
         | ((x & 2) << 2)  | ((y & 2) << 3) | ((z & 2) << 4)
         | ((x & 4) << 4)  | ((y & 4) << 5) | ((z & 4) << 6);
}

// ---------------- counting sort by morton cell: one block per batch ----------------
__global__ __launch_bounds__(512)
void sort_kernel(const float* __restrict__ xyz,
                 float* __restrict__ xs, int* __restrict__ so)
{
    __shared__ int cnt[CELLS];
    __shared__ int wsum[16];

    const int b    = blockIdx.x;
    const int tid  = threadIdx.x;
    const int lane = tid & 31;
    const int wid  = tid >> 5;
    const float* x = xyz + (size_t)b * NPTS * 3;
    float* xout    = xs + (size_t)b * NPTS * 3;
    int*   sout    = so + (size_t)b * NPTS;

    cnt[tid] = 0;
    __syncthreads();

    int mycell[32];
#pragma unroll
    for (int i = 0; i < 32; i++) {
        int j = tid + i * 512;
        int c = morton3(cellco(x[3 * j + 0]), cellco(x[3 * j + 1]), cellco(x[3 * j + 2]));
        mycell[i] = c;
        atomicAdd(&cnt[c], 1);
    }
    __syncthreads();

    // exclusive prefix sum over 512 counts
    int v = cnt[tid];
    int incl = v;
#pragma unroll
    for (int o = 1; o < 32; o <<= 1) {
        int u = __shfl_up_sync(0xFFFFFFFFu, incl, o);
        if (lane >= o) incl += u;
    }
    if (lane == 31) wsum[wid] = incl;
    __syncthreads();
    if (wid == 0 && lane < 16) {
        int w = wsum[lane];
        int wi = w;
#pragma unroll
        for (int o = 1; o < 16; o <<= 1) {
            int u = __shfl_up_sync(0x0000FFFFu, wi, o);
            if (lane >= o) wi += u;
        }
        wsum[lane] = wi - w;                       // exclusive warp base
    }
    __syncthreads();
    int excl = incl - v + wsum[wid];
    __syncthreads();
    cnt[tid] = excl;                               // running offsets
    __syncthreads();

#pragma unroll
    for (int i = 0; i < 32; i++) {
        int j = tid + i * 512;
        int pos = atomicAdd(&cnt[mycell[i]], 1);
        xout[3 * pos + 0] = x[3 * j + 0];
        xout[3 * pos + 1] = x[3 * j + 1];
        xout[3 * pos + 2] = x[3 * j + 2];
        sout[pos] = j;
    }
}

// ---------------- FPS: one block per batch, spatially pruned (R8/R11 winner) ----------------
__global__ __launch_bounds__(FPS_THREADS, 1)
void fps_kernel(const float* __restrict__ xyz,       // orig (for first centroid)
                const float* __restrict__ xs,        // sorted coords
                const int*   __restrict__ so,        // sorted -> orig index
                float* __restrict__ newxyz)
{
    extern __shared__ char smemraw[];
    float2* sdist2 = reinterpret_cast<float2*>(smemraw);            // 8192 x 8B
    uint2*  skey2  = reinterpret_cast<uint2*>(smemraw + NPTS / 2 * sizeof(float2));
    __shared__ unsigned sval[FPS_WARPS];
    __shared__ unsigned sidx[FPS_WARPS];

    const int b    = blockIdx.x;
    const int tid  = threadIdx.x;
    const int lane = tid & 31;
    const int wid  = tid >> 5;
    const float* x  = xs + (size_t)b * NPTS * 3;
    const int*   sg = so + (size_t)b * NPTS;

    u64 px[FPS_PAIRS], py[FPS_PAIRS], pz[FPS_PAIRS];
    float bx0 = 1e30f, bx1 = -1e30f, by0 = 1e30f, by1 = -1e30f, bz0 = 1e30f, bz1 = -1e30f;
#pragma unroll
    for (int i = 0; i < FPS_PAIRS; i++) {
        const float2* c6 = reinterpret_cast<const float2*>(x + 6 * (16 * tid + i));
        float2 a = c6[0], bb = c6[1], cc = c6[2];    // x0 y0 | z0 x1 | y1 z1
        px[i] = f2_pack(a.x, bb.y);
        py[i] = f2_pack(a.y, cc.x);
        pz[i] = f2_pack(bb.x, cc.y);
        bx0 = fminf(bx0, fminf(a.x, bb.y)); bx1 = fmaxf(bx1, fmaxf(a.x, bb.y));
        by0 = fminf(by0, fminf(a.y, cc.x)); by1 = fmaxf(by1, fmaxf(a.y, cc.x));
        bz0 = fminf(bz0, fminf(bb.x, cc.y)); bz1 = fmaxf(bz1, fmaxf(bb.x, cc.y));
        int slot = tid + 512 * i;
        sdist2[slot] = make_float2(1e10f, 1e10f);
        int pos0 = 32 * tid + 2 * i;
        skey2[slot] = make_uint2(((unsigned)sg[pos0] << 14) | (unsigned)pos0,
                                 ((unsigned)sg[pos0 + 1] << 14) | (unsigned)(pos0 + 1));
    }
    __syncthreads();

    // first farthest = ORIGINAL index 0
    const float* x0p = xyz + (size_t)b * NPTS * 3;
    float cx = x0p[0], cy = x0p[1], cz = x0p[2];
    float gmaxf = 1e30f;
    float vmax  = -1.0f;                             // cached max of this thread's 32 d

    for (int s = 0; s < NPOINT; s++) {
        if (tid == 0) {
            float* o = newxyz + (size_t)(b * NPOINT + s) * 3;
            o[0] = cx; o[1] = cy; o[2] = cz;
        }
        // min squared distance from c to this thread's bbox (conservative margin)
        float ex = fmaxf(fmaxf(bx0 - cx, cx - bx1), 0.0f);
        float ey = fmaxf(fmaxf(by0 - cy, cy - by1), 0.0f);
        float ez = fmaxf(fmaxf(bz0 - cz, cz - bz1), 0.0f);
        float bd2 = ex * ex + ey * ey + ez * ez;
        bool touched = !(bd2 > gmaxf * 1.00002f);

        if (__any_sync(0xFFFFFFFFu, touched)) {      // warp-uniform gate
            const u64 ncx = f2_pack(-cx, -cx);
            const u64 ncy = f2_pack(-cy, -cy);
            const u64 ncz = f2_pack(-cz, -cz);
            float v0 = -1.0f, v1 = -1.0f;
#pragma unroll
            for (int i = 0; i < FPS_PAIRS; i++) {
                int slot = tid + 512 * i;
                u64 dx, dy, dz, acc;
                f2_add(dx, px[i], ncx);
                f2_add(dy, py[i], ncy);
                f2_add(dz, pz[i], ncz);
                f2_mul(dx, dx, dx);
                f2_mul(dy, dy, dy);
                f2_mul(dz, dz, dz);
                f2_add(acc, dx, dy);
                f2_add(acc, acc, dz);
                float d0, d1;
                f2_unpack(d0, d1, acc);
                float2 dd = sdist2[slot];
                float n0 = fminf(dd.x, d0);
                float n1 = fminf(dd.y, d1);
                sdist2[slot] = make_float2(n0, n1);
                v0 = fmaxf(v0, n0);
                v1 = fmaxf(v1, n1);
            }
            vmax = fmaxf(v0, v1);
        }

        const unsigned bits = __float_as_uint(vmax); // positive: bit order == value order
        const unsigned wmax = __reduce_max_sync(0xFFFFFFFFu, bits);
        if (lane == 0) sval[wid] = wmax;
        __syncthreads();                             // bar1

        const unsigned gbits = __reduce_max_sync(0xFFFFFFFFu, sval[lane & (FPS_WARPS - 1)]);

        if (lane == 0) sidx[wid] = 0xFFFFFFFFu;      // default: not a winner
        if (wmax == gbits) {                         // winner warp(s) rescan own entries
            unsigned cand = 0xFFFFFFFFu;
#pragma unroll
            for (int i = 0; i < FPS_PAIRS; i++) {
                int slot = tid + 512 * i;
                float2 dd = sdist2[slot];
                uint2  kk = skey2[slot];
                if (__float_as_uint(dd.x) == gbits) cand = min(cand, kk.x);
                if (__float_as_uint(dd.y) == gbits) cand = min(cand, kk.y);
            }
            cand = __reduce_min_sync(0xFFFFFFFFu, cand);
            if (lane == 0) sidx[wid] = cand;
        }
        __syncthreads();                             // bar2

        const unsigned gc = __reduce_min_sync(0xFFFFFFFFu, sidx[lane & (FPS_WARPS - 1)]);
        const int pos = (int)(gc & 0x3FFFu);
        cx = __ldg(x + 3 * pos + 0);
        cy = __ldg(x + 3 * pos + 1);
        cz = __ldg(x + 3 * pos + 2);
        gmaxf = __uint_as_float(gbits);
    }
}

// ---------------- ball query + gather + feature build: one warp per center ----------------
__global__ __launch_bounds__(256)
void ballq_feat_kernel(const float* __restrict__ xyz,
                       const float* __restrict__ points,
                       const float* __restrict__ newxyz,
                       float* __restrict__ feat0)
{
    const float R2 = (float)(0.2 * 0.2);
    const int warp = threadIdx.x >> 5;
    const int lane = threadIdx.x & 31;
    const int gw   = blockIdx.x * 8 + warp;     // 0..8191 center id
    const int b    = gw >> 10;

    const float* x = xyz + (size_t)b * NPTS * 3;
    const float cx = newxyz[gw * 3 + 0];
    const float cy = newxyz[gw * 3 + 1];
    const float cz = newxyz[gw * 3 + 2];

    __shared__ int slist[8][NSAMPLE];

    int cnt = 0;
    for (int j0 = 0; j0 < NPTS; j0 += 32) {
        int j = j0 + lane;
        float dx = __fadd_rn(x[3 * j + 0], -cx);
        float dy = __fadd_rn(x[3 * j + 1], -cy);
        float dz = __fadd_rn(x[3 * j + 2], -cz);
        float d  = __fadd_rn(__fadd_rn(__fmul_rn(dx, dx), __fmul_rn(dy, dy)),
                             __fmul_rn(dz, dz));
        bool inb = !(d > R2);
        unsigned mask = __ballot_sync(0xFFFFFFFFu, inb);
        int pos = cnt + __popc(mask & ((1u << lane) - 1u));
        if (inb && pos < NSAMPLE) slist[warp][pos] = j;
        cnt += __popc(mask);
        if (cnt >= NSAMPLE) break;
    }
    __syncwarp();

    int m = cnt < NSAMPLE ? cnt : NSAMPLE;
    int idx = (lane < m) ? slist[warp][lane] : slist[warp][0];

    const float* p = points + (size_t)b * NPTS * 3;
    size_t o = (size_t)(gw * NSAMPLE + lane) * C0;
    feat0[o + 0] = x[3 * idx + 0] - cx;
    feat0[o + 1] = x[3 * idx + 1] - cy;
    feat0[o + 2] = x[3 * idx + 2] - cz;
    feat0[o + 3] = p[3 * idx + 0];
    feat0[o + 4] = p[3 * idx + 1];
    feat0[o + 5] = p[3 * idx + 2];
}

// ---------------- first conv(1x1): CIN=6, raw output ----------------
__global__ __launch_bounds__(256)
void layer1_kernel(const float* __restrict__ X, const float* __restrict__ W,
                   const float* __restrict__ Bb, float* __restrict__ Y)
{
    __shared__ __align__(16) float Ws[C1 * C0];
    __shared__ float Bs[C1];

    const int tid = threadIdx.x;
    for (int i = tid; i < C1 * C0; i += 256) Ws[i] = W[i];
    for (int i = tid; i < C1; i += 256) Bs[i] = Bb[i];
    __syncthreads();

    const size_t n = (size_t)blockIdx.x * 256 + tid;

    float xin[C0];
#pragma unroll
    for (int c = 0; c < C0; c++) xin[c] = X[n * C0 + c];

    float4* Y4 = reinterpret_cast<float4*>(Y + n * C1);
#pragma unroll 2
    for (int og = 0; og < C1 / 4; og++) {
        float acc[4];
#pragma unroll
        for (int u = 0; u < 4; u++) {
            acc[u] = Bs[4 * og + u];
#pragma unroll
            for (int c = 0; c < C0; c++) acc[u] += xin[c] * Ws[(4 * og + u) * C0 + c];
        }
        Y4[og] = make_float4(acc[0], acc[1], acc[2], acc[3]);
    }
}

// ---------------- packed-FFMA2 conv: CIN=64, COUT templated ----------------
template<int COUT>
__global__ __launch_bounds__(256)
void layer_packed_kernel(const float* __restrict__ X, const float* __restrict__ W,
                         const float* __restrict__ Bb,
                         const float* __restrict__ sA, const float* __restrict__ sB,
                         float* __restrict__ Y)
{
    constexpr int CIN = 64;
    constexpr int OP  = COUT / 2;                  // output pairs
    __shared__ __align__(16) u64 Ws2[CIN][OP];
    __shared__ __align__(16) u64 Bs2[OP];
    __shared__ float sAs[CIN], sBs[CIN];

    const int tid = threadIdx.x;

    for (int idx = tid; idx < CIN * OP; idx += 256) {
        int c  = idx / OP;
        int op = idx - c * OP;
        Ws2[c][op] = f2_pack(W[(2 * op) * CIN + c], W[(2 * op + 1) * CIN + c]);
    }
    for (int op = tid; op < OP; op += 256) Bs2[op] = f2_pack(Bb[2 * op], Bb[2 * op + 1]);
    for (int i = tid; i < CIN; i += 256) { sAs[i] = sA[i]; sBs[i] = sB[i]; }
    __syncthreads();

    const size_t n = (size_t)blockIdx.x * 256 + tid;

    float xin[CIN];
    {
        const float4* X4 = reinterpret_cast<const float4*>(X + n * CIN);
#pragma unroll
        for (int c4 = 0; c4 < CIN / 4; c4++) {
            float4 v = X4[c4];
            xin[4 * c4 + 0] = v.x; xin[4 * c4 + 1] = v.y;
            xin[4 * c4 + 2] = v.z; xin[4 * c4 + 3] = v.w;
        }
#pragma unroll
        for (int c = 0; c < CIN; c++)
            xin[c] = fmaxf(__fmaf_rn(xin[c], sAs[c], sBs[c]), 0.f);
    }

    float4* Y4 = reinterpret_cast<float4*>(Y + n * COUT);
#pragma unroll 1
    for (int og = 0; og < COUT / 16; og++) {
        u64 acc2[8];
#pragma unroll
        for (int k = 0; k < 8; k++) acc2[k] = Bs2[og * 8 + k];
#pragma unroll
        for (int c = 0; c < CIN; c++) {
            const u64 x2 = f2_pack(xin[c], xin[c]);
            const ulonglong2* wp = reinterpret_cast<const ulonglong2*>(&Ws2[c][og * 8]);
#pragma unroll
            for (int k4 = 0; k4 < 4; k4++) {
                ulonglong2 w = wp[k4];
                f2_fma(acc2[2 * k4 + 0], x2, w.x);
                f2_fma(acc2[2 * k4 + 1], x2, w.y);
            }
        }
#pragma unroll
        for (int q = 0; q < 4; q++) {
            float o0, o1, o2, o3;
            f2_unpack(o0, o1, acc2[2 * q + 0]);
            f2_unpack(o2, o3, acc2[2 * q + 1]);
            Y4[og * 4 + q] = make_float4(o0, o1, o2, o3);
        }
    }
}

// ---------------- per-channel sum/sumsq + fused BN finalize (last block) ----------------
template<int C>
__global__ __launch_bounds__(256)
void stats_kernel(const float* __restrict__ Y,
                  double* __restrict__ gsum, double* __restrict__ gsq,
                  const float* __restrict__ g, const float* __restrict__ be,
                  float* __restrict__ sA, float* __restrict__ sB,
                  int* __restrict__ ctr)
{
    __shared__ float ssum[C];
    __shared__ float ssq[C];
    __shared__ bool  slast;
    const int tid = threadIdx.x;
    for (int i = tid; i < C; i += 256) { ssum[i] = 0.f; ssq[i] = 0.f; }
    __syncthreads();

    const float4* Y4 = reinterpret_cast<const float4*>(Y);
    const size_t total4 = (size_t)NTOT * C / 4;
    const size_t stride = (size_t)gridDim.x * 256;      // 4*stride % C == 0 (C|1024)
    const size_t i0 = (size_t)blockIdx.x * 256 + tid;

    float s0 = 0.f, s1 = 0.f, s2 = 0.f, s3 = 0.f;
    float q0 = 0.f, q1 = 0.f, q2 = 0.f, q3 = 0.f;
    for (size_t i = i0; i < total4; i += stride) {
        float4 v = Y4[i];
        s0 += v.x; s1 += v.y; s2 += v.z; s3 += v.w;
        q0 = __fmaf_rn(v.x, v.x, q0); q1 = __fmaf_rn(v.y, v.y, q1);
        q2 = __fmaf_rn(v.z, v.z, q2); q3 = __fmaf_rn(v.w, v.w, q3);
    }
    const int cb = (int)((4 * i0) % C);
    atomicAdd(&ssum[cb + 0], s0); atomicAdd(&ssq[cb + 0], q0);
    atomicAdd(&ssum[cb + 1], s1); atomicAdd(&ssq[cb + 1], q1);
    atomicAdd(&ssum[cb + 2], s2); atomicAdd(&ssq[cb + 2], q2);
    atomicAdd(&ssum[cb + 3], s3); atomicAdd(&ssq[cb + 3], q3);
    __syncthreads();
    for (int c = tid; c < C; c += 256) {
        atomicAdd(&gsum[c], (double)ssum[c]);
        atomicAdd(&gsq[c],  (double)ssq[c]);
    }
    __threadfence();
    if (tid == 0) slast = (atomicAdd(ctr, 1) == (int)gridDim.x - 1);
    __syncthreads();
    if (slast && tid < C) {
        double mu  = gsum[tid] / (double)NTOT;
        double var = gsq[tid] / (double)NTOT - mu * mu;
        float rsig = rsqrtf((float)var + 1e-5f);
        float a = g[tid] * rsig;
        sA[tid] = a;
        sB[tid] = be[tid] - (float)mu * a;
    }
}

// ---------------- final BN + ReLU + max over K ----------------
__global__ __launch_bounds__(128)
void maxpool_kernel(const float* __restrict__ act3,
                    const float* __restrict__ sA, const float* __restrict__ sB,
                    float* __restrict__ out)
{
    const int bs = blockIdx.x;          // 0..8191
    const int c  = threadIdx.x;         // 0..127
    const float a = sA[c], b = sB[c];
    size_t base = (size_t)bs * NSAMPLE * C3;
    float m = -1e30f;
#pragma unroll 8
    for (int k = 0; k < NSAMPLE; k++) {
        float v = fmaxf(__fmaf_rn(__ldg(act3 + base + (size_t)k * C3 + c), a, b), 0.f);
        m = fmaxf(m, v);
    }
    out[(size_t)bs * C3 + c] = m;
}

__global__ void zero_stats(double* gsum, double* gsq, int* ctr)
{
    int i = threadIdx.x;
    if (i < 384) { gsum[i] = 0.0; gsq[i] = 0.0; }
    if (i < 3) ctr[i] = 0;
}

// ---------------- launch ----------------
extern "C" void kernel_launch(void* const* d_in, const int* in_sizes, int n_in,
                              void* d_out, int out_size)
{
    const float* xyz = (const float*)d_in[0];
    const float* pts = (const float*)d_in[1];
    const float* w0  = (const float*)d_in[2];
    const float* b0  = (const float*)d_in[3];
    const float* g0  = (const float*)d_in[4];
    const float* be0 = (const float*)d_in[5];
    const float* w1  = (const float*)d_in[6];
    const float* b1  = (const float*)d_in[7];
    const float* g1  = (const float*)d_in[8];
    const float* be1 = (const float*)d_in[9];
    const float* w2  = (const float*)d_in[10];
    const float* b2  = (const float*)d_in[11];
    const float* g2  = (const float*)d_in[12];
    const float* be2 = (const float*)d_in[13];

    float* out    = (float*)d_out;
    float* newxyz = out;                              // (8,1024,3)
    float* newpts = out + BATCH * NPOINT * 3;         // (8,1024,128)

    float *feat0, *act1, *act2, *act3, *sA, *sB, *xs;
    int *so, *ctr;
    double *gsum, *gsq;
    cudaGetSymbolAddress((void**)&xs,    g_sorted);
    cudaGetSymbolAddress((void**)&so,    g_sorig);
    cudaGetSymbolAddress((void**)&feat0, g_feat0);
    cudaGetSymbolAddress((void**)&act1,  g_act1);
    cudaGetSymbolAddress((void**)&act2,  g_act2);
    cudaGetSymbolAddress((void**)&act3,  g_act3);
    cudaGetSymbolAddress((void**)&gsum,  g_sum);
    cudaGetSymbolAddress((void**)&gsq,   g_sq);
    cudaGetSymbolAddress((void**)&sA,    g_sA);
    cudaGetSymbolAddress((void**)&sB,    g_sB);
    cudaGetSymbolAddress((void**)&ctr,   g_ctr);

    cudaFuncSetAttribute(fps_kernel,
                         cudaFuncAttributeMaxDynamicSharedMemorySize,
                         FPS_SMEM);

    // 1 pad: profiler captures launch index 3 -> ballq_feat_kernel this round
    // (pad 0, sort 1, fps 2, ballq 3)
    zero_stats<<<1, 384>>>(gsum, gsq, ctr);

    sort_kernel<<<BATCH, 512>>>(xyz, xs, so);
    fps_kernel<<<BATCH, FPS_THREADS, FPS_SMEM>>>(xyz, xs, so, newxyz);
    ballq_feat_kernel<<<(BATCH * NPOINT) / 8, 256>>>(xyz, pts, newxyz, feat0);

    layer1_kernel<<<NTOT / 256, 256>>>(feat0, w0, b0, act1);
    stats_kernel<C1><<<1184, 256>>>(act1, gsum + 0, gsq + 0,
                                    g0, be0, sA + 0, sB + 0, ctr + 0);

    layer_packed_kernel<C2><<<NTOT / 256, 256>>>(act1, w1, b1, sA + 0, sB + 0, act2);
    stats_kernel<C2><<<1184, 256>>>(act2, gsum + 128, gsq + 128,
                                    g1, be1, sA + 128, sB + 128, ctr + 1);

    layer_packed_kernel<C3><<<NTOT / 256, 256>>>(act2, w2, b2, sA + 128, sB + 128, act3);
    stats_kernel<C3><<<1184, 256>>>(act3, gsum + 256, gsq + 256,
                                    g2, be2, sA + 256, sB + 256, ctr + 2);

    maxpool_kernel<<<BATCH * NPOINT, 128>>>(act3, sA + 256, sB + 256, newpts);
}

// round 14
// speedup vs baseline: 1.1440x; 1.0299x over previous
#include <cuda_runtime.h>
#include <cuda_bf16.h>
#include <math.h>
#include <stdint.h>

// ---------------- problem constants ----------------
#define BATCH   8
#define NPTS    16384
#define NPOINT  1024
#define NSAMPLE 32
#define NTOT    (BATCH * NPOINT * NSAMPLE)   // 262144 rows through the MLP
#define C0      6
#define C1      64
#define C2      64
#define C3      128

#define FPS_THREADS 512
#define FPS_PAIRS   (NPTS / (2 * FPS_THREADS))   // 16 pairs -> 32 points per thread
#define FPS_WARPS   (FPS_THREADS / 32)           // 16
#define CELLS       512                          // 8x8x8 morton grid

#define FPS_SMEM    (NPTS / 2 * (sizeof(float2) + sizeof(uint2)))   // 128KB

typedef unsigned long long u64;

// ---------------- device scratch (no allocations allowed) ----------------
__device__ float  g_sorted[(size_t)BATCH * NPTS * 3];
__device__ int    g_sorig[(size_t)BATCH * NPTS];
__device__ float  g_feat0[(size_t)NTOT * C0];
__device__ float  g_act1[(size_t)NTOT * C1];
__device__ float  g_act2[(size_t)NTOT * C2];
__device__ float  g_act3[(size_t)NTOT * C3];
__device__ double g_sum[3 * 128];
__device__ double g_sq[3 * 128];
__device__ float  g_sA[3 * 128];
__device__ float  g_sB[3 * 128];
__device__ int    g_ctr[3];

// ---------------- packed f32x2 helpers (Blackwell) ----------------
__device__ __forceinline__ void f2_add(u64& o, u64 a, u64 b) {
    asm("add.rn.f32x2 %0, %1, %2;" : "=l"(o) : "l"(a), "l"(b));
}
__device__ __forceinline__ void f2_mul(u64& o, u64 a, u64 b) {
    asm("mul.rn.f32x2 %0, %1, %2;" : "=l"(o) : "l"(a), "l"(b));
}
__device__ __forceinline__ void f2_fma(u64& d, u64 a, u64 b) {
    asm("fma.rn.f32x2 %0, %1, %2, %3;" : "=l"(d) : "l"(a), "l"(b), "l"(d));
}
__device__ __forceinline__ u64 f2_pack(float lo, float hi) {
    u64 r;
    asm("mov.b64 %0, {%1, %2};" : "=l"(r) : "f"(lo), "f"(hi));
    return r;
}
__device__ __forceinline__ void f2_unpack(float& lo, float& hi, u64 v) {
    asm("mov.b64 {%0, %1}, %2;" : "=f"(lo), "=f"(hi) : "l"(v));
}

// ---------------- morton cell id (8x8x8) ----------------
__device__ __forceinline__ int cellco(float v) {
    int c = (int)(v * 8.0f);
    return c < 0 ? 0 : (c > 7 ? 7 : c);
}
__device__ __forceinline__ int morton3(int x, int y, int z) {
    return  (x & 1)        | ((y & 1) << 1) | ((z & 1) << 2)
         | ((x & 2) << 2)  | ((y & 2) << 3) | ((z & 2) << 4)
         | ((x & 4) << 4)  | ((y & 4) << 5) | ((z & 4) << 6);
}

// ---------------- counting sort by morton cell: one block per batch ----------------
__global__ __launch_bounds__(512)
void sort_kernel(const float* __restrict__ xyz,
                 float* __restrict__ xs, int* __restrict__ so)
{
    __shared__ int cnt[CELLS];
    __shared__ int wsum[16];

    const int b    = blockIdx.x;
    const int tid  = threadIdx.x;
    const int lane = tid & 31;
    const int wid  = tid >> 5;
    const float* x = xyz + (size_t)b * NPTS * 3;
    float* xout    = xs + (size_t)b * NPTS * 3;
    int*   sout    = so + (size_t)b * NPTS;

    cnt[tid] = 0;
    __syncthreads();

    int mycell[32];
#pragma unroll
    for (int i = 0; i < 32; i++) {
        int j = tid + i * 512;
        int c = morton3(cellco(x[3 * j + 0]), cellco(x[3 * j + 1]), cellco(x[3 * j + 2]));
        mycell[i] = c;
        atomicAdd(&cnt[c], 1);
    }
    __syncthreads();

    // exclusive prefix sum over 512 counts
    int v = cnt[tid];
    int incl = v;
#pragma unroll
    for (int o = 1; o < 32; o <<= 1) {
        int u = __shfl_up_sync(0xFFFFFFFFu, incl, o);
        if (lane >= o) incl += u;
    }
    if (lane == 31) wsum[wid] = incl;
    __syncthreads();
    if (wid == 0 && lane < 16) {
        int w = wsum[lane];
        int wi = w;
#pragma unroll
        for (int o = 1; o < 16; o <<= 1) {
            int u = __shfl_up_sync(0x0000FFFFu, wi, o);
            if (lane >= o) wi += u;
        }
        wsum[lane] = wi - w;                       // exclusive warp base
    }
    __syncthreads();
    int excl = incl - v + wsum[wid];
    __syncthreads();
    cnt[tid] = excl;                               // running offsets
    __syncthreads();

#pragma unroll
    for (int i = 0; i < 32; i++) {
        int j = tid + i * 512;
        int pos = atomicAdd(&cnt[mycell[i]], 1);
        xout[3 * pos + 0] = x[3 * j + 0];
        xout[3 * pos + 1] = x[3 * j + 1];
        xout[3 * pos + 2] = x[3 * j + 2];
        sout[pos] = j;
    }
}

// ---------------- FPS: one block per batch, spatially pruned (R8/R11 winner) ----------------
__global__ __launch_bounds__(FPS_THREADS, 1)
void fps_kernel(const float* __restrict__ xyz,       // orig (for first centroid)
                const float* __restrict__ xs,        // sorted coords
                const int*   __restrict__ so,        // sorted -> orig index
                float* __restrict__ newxyz)
{
    extern __shared__ char smemraw[];
    float2* sdist2 = reinterpret_cast<float2*>(smemraw);            // 8192 x 8B
    uint2*  skey2  = reinterpret_cast<uint2*>(smemraw + NPTS / 2 * sizeof(float2));
    __shared__ unsigned sval[FPS_WARPS];
    __shared__ unsigned sidx[FPS_WARPS];

    const int b    = blockIdx.x;
    const int tid  = threadIdx.x;
    const int lane = tid & 31;
    const int wid  = tid >> 5;
    const float* x  = xs + (size_t)b * NPTS * 3;
    const int*   sg = so + (size_t)b * NPTS;

    u64 px[FPS_PAIRS], py[FPS_PAIRS], pz[FPS_PAIRS];
    float bx0 = 1e30f, bx1 = -1e30f, by0 = 1e30f, by1 = -1e30f, bz0 = 1e30f, bz1 = -1e30f;
#pragma unroll
    for (int i = 0; i < FPS_PAIRS; i++) {
        const float2* c6 = reinterpret_cast<const float2*>(x + 6 * (16 * tid + i));
        float2 a = c6[0], bb = c6[1], cc = c6[2];    // x0 y0 | z0 x1 | y1 z1
        px[i] = f2_pack(a.x, bb.y);
        py[i] = f2_pack(a.y, cc.x);
        pz[i] = f2_pack(bb.x, cc.y);
        bx0 = fminf(bx0, fminf(a.x, bb.y)); bx1 = fmaxf(bx1, fmaxf(a.x, bb.y));
        by0 = fminf(by0, fminf(a.y, cc.x)); by1 = fmaxf(by1, fmaxf(a.y, cc.x));
        bz0 = fminf(bz0, fminf(bb.x, cc.y)); bz1 = fmaxf(bz1, fmaxf(bb.x, cc.y));
        int slot = tid + 512 * i;
        sdist2[slot] = make_float2(1e10f, 1e10f);
        int pos0 = 32 * tid + 2 * i;
        skey2[slot] = make_uint2(((unsigned)sg[pos0] << 14) | (unsigned)pos0,
                                 ((unsigned)sg[pos0 + 1] << 14) | (unsigned)(pos0 + 1));
    }
    __syncthreads();

    // first farthest = ORIGINAL index 0
    const float* x0p = xyz + (size_t)b * NPTS * 3;
    float cx = x0p[0], cy = x0p[1], cz = x0p[2];
    float gmaxf = 1e30f;
    float vmax  = -1.0f;                             // cached max of this thread's 32 d

    for (int s = 0; s < NPOINT; s++) {
        if (tid == 0) {
            float* o = newxyz + (size_t)(b * NPOINT + s) * 3;
            o[0] = cx; o[1] = cy; o[2] = cz;
        }
        // min squared distance from c to this thread's bbox (conservative margin)
        float ex = fmaxf(fmaxf(bx0 - cx, cx - bx1), 0.0f);
        float ey = fmaxf(fmaxf(by0 - cy, cy - by1), 0.0f);
        float ez = fmaxf(fmaxf(bz0 - cz, cz - bz1), 0.0f);
        float bd2 = ex * ex + ey * ey + ez * ez;
        bool touched = !(bd2 > gmaxf * 1.00002f);

        if (__any_sync(0xFFFFFFFFu, touched)) {      // warp-uniform gate
            const u64 ncx = f2_pack(-cx, -cx);
            const u64 ncy = f2_pack(-cy, -cy);
            const u64 ncz = f2_pack(-cz, -cz);
            float v0 = -1.0f, v1 = -1.0f;
#pragma unroll
            for (int i = 0; i < FPS_PAIRS; i++) {
                int slot = tid + 512 * i;
                u64 dx, dy, dz, acc;
                f2_add(dx, px[i], ncx);
                f2_add(dy, py[i], ncy);
                f2_add(dz, pz[i], ncz);
                f2_mul(dx, dx, dx);
                f2_mul(dy, dy, dy);
                f2_mul(dz, dz, dz);
                f2_add(acc, dx, dy);
                f2_add(acc, acc, dz);
                float d0, d1;
                f2_unpack(d0, d1, acc);
                float2 dd = sdist2[slot];
                float n0 = fminf(dd.x, d0);
                float n1 = fminf(dd.y, d1);
                sdist2[slot] = make_float2(n0, n1);
                v0 = fmaxf(v0, n0);
                v1 = fmaxf(v1, n1);
            }
            vmax = fmaxf(v0, v1);
        }

        const unsigned bits = __float_as_uint(vmax); // positive: bit order == value order
        const unsigned wmax = __reduce_max_sync(0xFFFFFFFFu, bits);
        if (lane == 0) sval[wid] = wmax;
        __syncthreads();                             // bar1

        const unsigned gbits = __reduce_max_sync(0xFFFFFFFFu, sval[lane & (FPS_WARPS - 1)]);

        if (lane == 0) sidx[wid] = 0xFFFFFFFFu;      // default: not a winner
        if (wmax == gbits) {                         // winner warp(s) rescan own entries
            unsigned cand = 0xFFFFFFFFu;
#pragma unroll
            for (int i = 0; i < FPS_PAIRS; i++) {
                int slot = tid + 512 * i;
                float2 dd = sdist2[slot];
                uint2  kk = skey2[slot];
                if (__float_as_uint(dd.x) == gbits) cand = min(cand, kk.x);
                if (__float_as_uint(dd.y) == gbits) cand = min(cand, kk.y);
            }
            cand = __reduce_min_sync(0xFFFFFFFFu, cand);
            if (lane == 0) sidx[wid] = cand;
        }
        __syncthreads();                             // bar2

        const unsigned gc = __reduce_min_sync(0xFFFFFFFFu, sidx[lane & (FPS_WARPS - 1)]);
        const int pos = (int)(gc & 0x3FFFu);
        cx = __ldg(x + 3 * pos + 0);
        cy = __ldg(x + 3 * pos + 1);
        cz = __ldg(x + 3 * pos + 2);
        gmaxf = __uint_as_float(gbits);
    }
}

// ---------------- ball query + gather + feature build: one BLOCK per center ----------------
// 128 threads scan 128 points/step in index order (exact first-32-by-index
// semantics via block-wide ordered ballot); uniform early exit.
__global__ __launch_bounds__(128)
void ballq_feat_kernel(const float* __restrict__ xyz,
                       const float* __restrict__ points,
                       const float* __restrict__ newxyz,
                       float* __restrict__ feat0)
{
    const float R2 = (float)(0.2 * 0.2);
    const int tid  = threadIdx.x;
    const int lane = tid & 31;
    const int wid  = tid >> 5;                  // 0..3
    const int gw   = blockIdx.x;                // 0..8191 center id
    const int b    = gw >> 10;

    const float* x = xyz + (size_t)b * NPTS * 3;
    const float cx = newxyz[gw * 3 + 0];
    const float cy = newxyz[gw * 3 + 1];
    const float cz = newxyz[gw * 3 + 2];

    __shared__ int slist[NSAMPLE];
    __shared__ int swcnt[2][4];

    int cnt = 0;
    for (int j0 = 0; j0 < NPTS; j0 += 128) {
        const int p = (j0 >> 7) & 1;            // parity double-buffer
        int j = j0 + tid;
        float dx = __fadd_rn(x[3 * j + 0], -cx);
        float dy = __fadd_rn(x[3 * j + 1], -cy);
        float dz = __fadd_rn(x[3 * j + 2], -cz);
        float d  = __fadd_rn(__fadd_rn(__fmul_rn(dx, dx), __fmul_rn(dy, dy)),
                             __fmul_rn(dz, dz));
        bool inb = !(d > R2);
        unsigned mask = __ballot_sync(0xFFFFFFFFu, inb);
        if (lane == 0) swcnt[p][wid] = __popc(mask);
        __syncthreads();
        int c0 = swcnt[p][0], c1 = swcnt[p][1], c2 = swcnt[p][2], c3 = swcnt[p][3];
        int base = cnt;
        if (wid > 0) base += c0;
        if (wid > 1) base += c1;
        if (wid > 2) base += c2;
        int pos = base + __popc(mask & ((1u << lane) - 1u));
        if (inb && pos < NSAMPLE) slist[pos] = j;
        cnt += c0 + c1 + c2 + c3;               // uniform across block
        if (cnt >= NSAMPLE) break;              // uniform break
    }
    __syncthreads();                            // slist visible to warp 0

    if (wid == 0) {
        int m = cnt < NSAMPLE ? cnt : NSAMPLE;
        int idx = (lane < m) ? slist[lane] : slist[0];
        const float* pp = points + (size_t)b * NPTS * 3;
        size_t o = (size_t)(gw * NSAMPLE + lane) * C0;
        feat0[o + 0] = x[3 * idx + 0] - cx;
        feat0[o + 1] = x[3 * idx + 1] - cy;
        feat0[o + 2] = x[3 * idx + 2] - cz;
        feat0[o + 3] = pp[3 * idx + 0];
        feat0[o + 4] = pp[3 * idx + 1];
        feat0[o + 5] = pp[3 * idx + 2];
    }
}

// ---------------- first conv(1x1): CIN=6, raw output ----------------
__global__ __launch_bounds__(256)
void layer1_kernel(const float* __restrict__ X, const float* __restrict__ W,
                   const float* __restrict__ Bb, float* __restrict__ Y)
{
    __shared__ __align__(16) float Ws[C1 * C0];
    __shared__ float Bs[C1];

    const int tid = threadIdx.x;
    for (int i = tid; i < C1 * C0; i += 256) Ws[i] = W[i];
    for (int i = tid; i < C1; i += 256) Bs[i] = Bb[i];
    __syncthreads();

    const size_t n = (size_t)blockIdx.x * 256 + tid;

    float xin[C0];
#pragma unroll
    for (int c = 0; c < C0; c++) xin[c] = X[n * C0 + c];

    float4* Y4 = reinterpret_cast<float4*>(Y + n * C1);
#pragma unroll 2
    for (int og = 0; og < C1 / 4; og++) {
        float acc[4];
#pragma unroll
        for (int u = 0; u < 4; u++) {
            acc[u] = Bs[4 * og + u];
#pragma unroll
            for (int c = 0; c < C0; c++) acc[u] += xin[c] * Ws[(4 * og + u) * C0 + c];
        }
        Y4[og] = make_float4(acc[0], acc[1], acc[2], acc[3]);
    }
}

// ---------------- packed-FFMA2 conv: CIN=64, COUT templated ----------------
template<int COUT>
__global__ __launch_bounds__(256)
void layer_packed_kernel(const float* __restrict__ X, const float* __restrict__ W,
                         const float* __restrict__ Bb,
                         const float* __restrict__ sA, const float* __restrict__ sB,
                         float* __restrict__ Y)
{
    constexpr int CIN = 64;
    constexpr int OP  = COUT / 2;                  // output pairs
    __shared__ __align__(16) u64 Ws2[CIN][OP];
    __shared__ __align__(16) u64 Bs2[OP];
    __shared__ float sAs[CIN], sBs[CIN];

    const int tid = threadIdx.x;

    for (int idx = tid; idx < CIN * OP; idx += 256) {
        int c  = idx / OP;
        int op = idx - c * OP;
        Ws2[c][op] = f2_pack(W[(2 * op) * CIN + c], W[(2 * op + 1) * CIN + c]);
    }
    for (int op = tid; op < OP; op += 256) Bs2[op] = f2_pack(Bb[2 * op], Bb[2 * op + 1]);
    for (int i = tid; i < CIN; i += 256) { sAs[i] = sA[i]; sBs[i] = sB[i]; }
    __syncthreads();

    const size_t n = (size_t)blockIdx.x * 256 + tid;

    float xin[CIN];
    {
        const float4* X4 = reinterpret_cast<const float4*>(X + n * CIN);
#pragma unroll
        for (int c4 = 0; c4 < CIN / 4; c4++) {
            float4 v = X4[c4];
            xin[4 * c4 + 0] = v.x; xin[4 * c4 + 1] = v.y;
            xin[4 * c4 + 2] = v.z; xin[4 * c4 + 3] = v.w;
        }
#pragma unroll
        for (int c = 0; c < CIN; c++)
            xin[c] = fmaxf(__fmaf_rn(xin[c], sAs[c], sBs[c]), 0.f);
    }

    float4* Y4 = reinterpret_cast<float4*>(Y + n * COUT);
#pragma unroll 1
    for (int og = 0; og < COUT / 16; og++) {
        u64 acc2[8];
#pragma unroll
        for (int k = 0; k < 8; k++) acc2[k] = Bs2[og * 8 + k];
#pragma unroll
        for (int c = 0; c < CIN; c++) {
            const u64 x2 = f2_pack(xin[c], xin[c]);
            const ulonglong2* wp = reinterpret_cast<const ulonglong2*>(&Ws2[c][og * 8]);
#pragma unroll
            for (int k4 = 0; k4 < 4; k4++) {
                ulonglong2 w = wp[k4];
                f2_fma(acc2[2 * k4 + 0], x2, w.x);
                f2_fma(acc2[2 * k4 + 1], x2, w.y);
            }
        }
#pragma unroll
        for (int q = 0; q < 4; q++) {
            float o0, o1, o2, o3;
            f2_unpack(o0, o1, acc2[2 * q + 0]);
            f2_unpack(o2, o3, acc2[2 * q + 1]);
            Y4[og * 4 + q] = make_float4(o0, o1, o2, o3);
        }
    }
}

// ---------------- per-channel sum/sumsq + fused BN finalize (last block) ----------------
template<int C>
__global__ __launch_bounds__(256)
void stats_kernel(const float* __restrict__ Y,
                  double* __restrict__ gsum, double* __restrict__ gsq,
                  const float* __restrict__ g, const float* __restrict__ be,
                  float* __restrict__ sA, float* __restrict__ sB,
                  int* __restrict__ ctr)
{
    __shared__ float ssum[C];
    __shared__ float ssq[C];
    __shared__ bool  slast;
    const int tid = threadIdx.x;
    for (int i = tid; i < C; i += 256) { ssum[i] = 0.f; ssq[i] = 0.f; }
    __syncthreads();

    const float4* Y4 = reinterpret_cast<const float4*>(Y);
    const size_t total4 = (size_t)NTOT * C / 4;
    const size_t stride = (size_t)gridDim.x * 256;      // 4*stride % C == 0 (C|1024)
    const size_t i0 = (size_t)blockIdx.x * 256 + tid;

    float s0 = 0.f, s1 = 0.f, s2 = 0.f, s3 = 0.f;
    float q0 = 0.f, q1 = 0.f, q2 = 0.f, q3 = 0.f;
    for (size_t i = i0; i < total4; i += stride) {
        float4 v = Y4[i];
        s0 += v.x; s1 += v.y; s2 += v.z; s3 += v.w;
        q0 = __fmaf_rn(v.x, v.x, q0); q1 = __fmaf_rn(v.y, v.y, q1);
        q2 = __fmaf_rn(v.z, v.z, q2); q3 = __fmaf_rn(v.w, v.w, q3);
    }
    const int cb = (int)((4 * i0) % C);
    atomicAdd(&ssum[cb + 0], s0); atomicAdd(&ssq[cb + 0], q0);
    atomicAdd(&ssum[cb + 1], s1); atomicAdd(&ssq[cb + 1], q1);
    atomicAdd(&ssum[cb + 2], s2); atomicAdd(&ssq[cb + 2], q2);
    atomicAdd(&ssum[cb + 3], s3); atomicAdd(&ssq[cb + 3], q3);
    __syncthreads();
    for (int c = tid; c < C; c += 256) {
        atomicAdd(&gsum[c], (double)ssum[c]);
        atomicAdd(&gsq[c],  (double)ssq[c]);
    }
    __threadfence();
    if (tid == 0) slast = (atomicAdd(ctr, 1) == (int)gridDim.x - 1);
    __syncthreads();
    if (slast && tid < C) {
        double mu  = gsum[tid] / (double)NTOT;
        double var = gsq[tid] / (double)NTOT - mu * mu;
        float rsig = rsqrtf((float)var + 1e-5f);
        float a = g[tid] * rsig;
        sA[tid] = a;
        sB[tid] = be[tid] - (float)mu * a;
    }
}

// ---------------- final BN + ReLU + max over K ----------------
__global__ __launch_bounds__(128)
void maxpool_kernel(const float* __restrict__ act3,
                    const float* __restrict__ sA, const float* __restrict__ sB,
                    float* __restrict__ out)
{
    const int bs = blockIdx.x;          // 0..8191
    const int c  = threadIdx.x;         // 0..127
    const float a = sA[c], b = sB[c];
    size_t base = (size_t)bs * NSAMPLE * C3;
    float m = -1e30f;
#pragma unroll 8
    for (int k = 0; k < NSAMPLE; k++) {
        float v = fmaxf(__fmaf_rn(__ldg(act3 + base + (size_t)k * C3 + c), a, b), 0.f);
        m = fmaxf(m, v);
    }
    out[(size_t)bs * C3 + c] = m;
}

__global__ void zero_stats(double* gsum, double* gsq, int* ctr)
{
    int i = threadIdx.x;
    if (i < 384) { gsum[i] = 0.0; gsq[i] = 0.0; }
    if (i < 3) ctr[i] = 0;
}

// ---------------- launch ----------------
extern "C" void kernel_launch(void* const* d_in, const int* in_sizes, int n_in,
                              void* d_out, int out_size)
{
    const float* xyz = (const float*)d_in[0];
    const float* pts = (const float*)d_in[1];
    const float* w0  = (const float*)d_in[2];
    const float* b0  = (const float*)d_in[3];
    const float* g0  = (const float*)d_in[4];
    const float* be0 = (const float*)d_in[5];
    const float* w1  = (const float*)d_in[6];
    const float* b1  = (const float*)d_in[7];
    const float* g1  = (const float*)d_in[8];
    const float* be1 = (const float*)d_in[9];
    const float* w2  = (const float*)d_in[10];
    const float* b2  = (const float*)d_in[11];
    const float* g2  = (const float*)d_in[12];
    const float* be2 = (const float*)d_in[13];

    float* out    = (float*)d_out;
    float* newxyz = out;                              // (8,1024,3)
    float* newpts = out + BATCH * NPOINT * 3;         // (8,1024,128)

    float *feat0, *act1, *act2, *act3, *sA, *sB, *xs;
    int *so, *ctr;
    double *gsum, *gsq;
    cudaGetSymbolAddress((void**)&xs,    g_sorted);
    cudaGetSymbolAddress((void**)&so,    g_sorig);
    cudaGetSymbolAddress((void**)&feat0, g_feat0);
    cudaGetSymbolAddress((void**)&act1,  g_act1);
    cudaGetSymbolAddress((void**)&act2,  g_act2);
    cudaGetSymbolAddress((void**)&act3,  g_act3);
    cudaGetSymbolAddress((void**)&gsum,  g_sum);
    cudaGetSymbolAddress((void**)&gsq,   g_sq);
    cudaGetSymbolAddress((void**)&sA,    g_sA);
    cudaGetSymbolAddress((void**)&sB,    g_sB);
    cudaGetSymbolAddress((void**)&ctr,   g_ctr);

    cudaFuncSetAttribute(fps_kernel,
                         cudaFuncAttributeMaxDynamicSharedMemorySize,
                         FPS_SMEM);

    // 1 pad: profiler captures launch index 3 -> ballq_feat_kernel
    // (pad 0, sort 1, fps 2, ballq 3)
    zero_stats<<<1, 384>>>(gsum, gsq, ctr);

    sort_kernel<<<BATCH, 512>>>(xyz, xs, so);
    fps_kernel<<<BATCH, FPS_THREADS, FPS_SMEM>>>(xyz, xs, so, newxyz);
    ballq_feat_kernel<<<BATCH * NPOINT, 128>>>(xyz, pts, newxyz, feat0);

    layer1_kernel<<<NTOT / 256, 256>>>(feat0, w0, b0, act1);
    stats_kernel<C1><<<1184, 256>>>(act1, gsum + 0, gsq + 0,
                                    g0, be0, sA + 0, sB + 0, ctr + 0);

    layer_packed_kernel<C2><<<NTOT / 256, 256>>>(act1, w1, b1, sA + 0, sB + 0, act2);
    stats_kernel<C2><<<1184, 256>>>(act2, gsum + 128, gsq + 128,
                                    g1, be1, sA + 128, sB + 128, ctr + 1);

    layer_packed_kernel<C3><<<NTOT / 256, 256>>>(act2, w2, b2, sA + 128, sB + 128, act3);
    stats_kernel<C3><<<1184, 256>>>(act3, gsum + 256, gsq + 256,
                                    g2, be2, sA + 256, sB + 256, ctr + 2);

    maxpool_kernel<<<BATCH * NPOINT, 128>>>(act3, sA + 256, sB + 256, newpts);
}